// round 1
// baseline (speedup 1.0000x reference)
#include <cuda_runtime.h>

#define T_LEN 16384
#define NXW   128
#define NH    512
#define STEPS (T_LEN - NXW)       /* 16256 */
#define NROWS (4 * NH)            /* 2048 gate rows */

#define NCTA  128
#define TPB   512                 /* 16 warps */
#define ROWS_PER_CTA (NROWS / NCTA)   /* 16 */
#define HPC          (NH / NCTA)      /* 4 h-indices per CTA */

/* ---- static scratch (no runtime allocation allowed) ---- */
__device__ __align__(16) float g_XG[(size_t)NROWS * STEPS];   /* [row][t], row = h*4+gate */
__device__ __align__(16) float g_H[(size_t)(STEPS + 1) * NH]; /* row t = h after step t-1 */
__device__ unsigned g_counter;

/* =================== init =================== */
__global__ void init_kernel() {
    int i = blockIdx.x * blockDim.x + threadIdx.x;
    if (i < NH) g_H[i] = 0.0f;
    if (i == 0) g_counter = 0u;
}

/* =================== gate precompute =================== */
/* XG[row][t] = b_g[h] + sum_k W_g[h,k] * x[t+k],  row = h*4+g */
#define GT_TPB  128
#define GT_TT   512     /* t per block: 4 per thread */
#define GT_ROWS 16

__global__ void __launch_bounds__(GT_TPB) gates_kernel(
    const float* __restrict__ x,
    const float* __restrict__ Wf, const float* __restrict__ Wi,
    const float* __restrict__ Wo, const float* __restrict__ Wc,
    const float* __restrict__ bf, const float* __restrict__ bi,
    const float* __restrict__ bo, const float* __restrict__ bc)
{
    __shared__ float xs[GT_TT + NXW];          /* 640 */
    __shared__ float ws[GT_ROWS * NXW];        /* 8 KB */
    __shared__ float bs[GT_ROWS];

    const int tid = threadIdx.x;
    const int t0  = blockIdx.x * GT_TT;
    const int r0  = blockIdx.y * GT_ROWS;

    for (int i = tid; i < GT_TT + NXW; i += GT_TPB) {
        int xi = t0 + i;
        xs[i] = (xi < T_LEN) ? x[xi] : 0.0f;
    }
    for (int i = tid; i < GT_ROWS * NXW; i += GT_TPB) {
        int lr = i >> 7;          /* /128 */
        int k  = i & 127;
        int r  = r0 + lr;
        int g  = r & 3;
        int h  = r >> 2;
        const float* W = (g == 0) ? Wf : (g == 1) ? Wi : (g == 2) ? Wo : Wc;
        ws[i] = W[h * NXW + k];
    }
    if (tid < GT_ROWS) {
        int r = r0 + tid;
        int g = r & 3;
        int h = r >> 2;
        const float* B = (g == 0) ? bf : (g == 1) ? bi : (g == 2) ? bo : bc;
        bs[tid] = B[h];
    }
    __syncthreads();

    float acc0[GT_ROWS], acc1[GT_ROWS], acc2[GT_ROWS], acc3[GT_ROWS];
#pragma unroll
    for (int lr = 0; lr < GT_ROWS; lr++) { acc0[lr] = acc1[lr] = acc2[lr] = acc3[lr] = 0.0f; }

#pragma unroll 4
    for (int k = 0; k < NXW; k++) {
        float x0 = xs[tid + k];
        float x1 = xs[tid + 128 + k];
        float x2 = xs[tid + 256 + k];
        float x3 = xs[tid + 384 + k];
#pragma unroll
        for (int lr = 0; lr < GT_ROWS; lr++) {
            float w = ws[lr * NXW + k];
            acc0[lr] = fmaf(w, x0, acc0[lr]);
            acc1[lr] = fmaf(w, x1, acc1[lr]);
            acc2[lr] = fmaf(w, x2, acc2[lr]);
            acc3[lr] = fmaf(w, x3, acc3[lr]);
        }
    }

#pragma unroll
    for (int lr = 0; lr < GT_ROWS; lr++) {
        size_t base = (size_t)(r0 + lr) * STEPS;
        int t;
        t = t0 + tid;       if (t < STEPS) g_XG[base + t] = acc0[lr] + bs[lr];
        t = t0 + 128 + tid; if (t < STEPS) g_XG[base + t] = acc1[lr] + bs[lr];
        t = t0 + 256 + tid; if (t < STEPS) g_XG[base + t] = acc2[lr] + bs[lr];
        t = t0 + 384 + tid; if (t < STEPS) g_XG[base + t] = acc3[lr] + bs[lr];
    }
}

/* =================== recurrence =================== */
__device__ __forceinline__ float sigmoid_f(float v) {
    float e = __expf(-v);
    return __fdividef(1.0f, 1.0f + e);
}
__device__ __forceinline__ float tanh_f(float v) {
    float e = __expf(2.0f * v);
    return __fdividef(e - 1.0f, e + 1.0f);
}

__global__ void __launch_bounds__(TPB, 1) rec_kernel(
    const float* __restrict__ Uf, const float* __restrict__ Ui,
    const float* __restrict__ Uo, const float* __restrict__ Uc)
{
    const int cta  = blockIdx.x;
    const int tid  = threadIdx.x;
    const int w    = tid >> 5;
    const int lane = tid & 31;

    const int row   = cta * ROWS_PER_CTA + w;   /* global gate row = h*4+g */
    const int g     = row & 3;
    const int h_idx = row >> 2;

    const float* U = ((g == 0) ? Uf : (g == 1) ? Ui : (g == 2) ? Uo : Uc)
                     + (size_t)h_idx * NH + lane * 16;
    const float4 u0 = *(const float4*)(U + 0);
    const float4 u1 = *(const float4*)(U + 4);
    const float4 u2 = *(const float4*)(U + 8);
    const float4 u3 = *(const float4*)(U + 12);

    __shared__ float sdots[ROWS_PER_CTA];
    __shared__ __align__(16) float sh[HPC];

    float c = 0.0f;                              /* cell state lives in threads 0..3 */
    const float* xgp = g_XG + (size_t)row * STEPS;
    float xg_cur = (lane == 0) ? __ldcg(xgp) : 0.0f;

    for (int t = 0; t < STEPS; t++) {
        /* prefetch next step's gate precompute (independent of h) */
        float xg_next = 0.0f;
        if (lane == 0 && t + 1 < STEPS) xg_next = __ldcg(xgp + t + 1);

        /* wait until all CTAs published h for step t-1 (g_H row t) */
        if (t > 0 && tid == 0) {
            unsigned target = (unsigned)NCTA * (unsigned)t;
            unsigned v;
            do {
                asm volatile("ld.acquire.gpu.global.u32 %0, [%1];"
                             : "=r"(v) : "l"(&g_counter) : "memory");
            } while (v < target);
        }
        __syncthreads();

        /* load h_prev (512 floats, L2 resident) */
        const float4* hp = (const float4*)(g_H + (size_t)t * NH) + lane * 4;
        float4 h0 = __ldcg(hp + 0);
        float4 h1 = __ldcg(hp + 1);
        float4 h2 = __ldcg(hp + 2);
        float4 h3 = __ldcg(hp + 3);

        float a = u0.x * h0.x;
        a = fmaf(u0.y, h0.y, a); a = fmaf(u0.z, h0.z, a); a = fmaf(u0.w, h0.w, a);
        float b = u1.x * h1.x;
        b = fmaf(u1.y, h1.y, b); b = fmaf(u1.z, h1.z, b); b = fmaf(u1.w, h1.w, b);
        a = fmaf(u2.x, h2.x, a); a = fmaf(u2.y, h2.y, a);
        a = fmaf(u2.z, h2.z, a); a = fmaf(u2.w, h2.w, a);
        b = fmaf(u3.x, h3.x, b); b = fmaf(u3.y, h3.y, b);
        b = fmaf(u3.z, h3.z, b); b = fmaf(u3.w, h3.w, b);
        a += b;

        a += __shfl_xor_sync(0xffffffffu, a, 16);
        a += __shfl_xor_sync(0xffffffffu, a, 8);
        a += __shfl_xor_sync(0xffffffffu, a, 4);
        a += __shfl_xor_sync(0xffffffffu, a, 2);
        a += __shfl_xor_sync(0xffffffffu, a, 1);

        if (lane == 0) sdots[w] = a + xg_cur;
        xg_cur = xg_next;
        __syncthreads();

        if (tid < HPC) {
            float ff = sigmoid_f(sdots[tid * 4 + 0]);
            float ii = sigmoid_f(sdots[tid * 4 + 1]);
            float oo = sigmoid_f(sdots[tid * 4 + 2]);
            float gg = tanh_f(sdots[tid * 4 + 3]);
            c = fmaf(ff, c, ii * gg);
            sh[tid] = oo * tanh_f(c);
            __syncwarp(0x0000000Fu);
            if (tid == 0) {
                float4 hv = *(const float4*)sh;
                __stcg(((float4*)(g_H + (size_t)(t + 1) * NH)) + cta, hv);
                unsigned one = 1u;
                asm volatile("red.release.gpu.global.add.u32 [%0], %1;"
                             :: "l"(&g_counter), "r"(one) : "memory");
            }
        }
    }
}

/* =================== output GEMV =================== */
__global__ void __launch_bounds__(256) out_kernel(
    const float* __restrict__ Ahy, const float* __restrict__ by,
    float* __restrict__ out)
{
    const int w    = threadIdx.x >> 5;
    const int lane = threadIdx.x & 31;
    const int t    = blockIdx.x * 8 + w;
    if (t >= STEPS) return;

    const float4* hp = (const float4*)(g_H + (size_t)(t + 1) * NH) + lane * 4;
    const float4* ap = (const float4*)Ahy + lane * 4;
    float a = 0.0f;
#pragma unroll
    for (int j = 0; j < 4; j++) {
        float4 hv = hp[j];
        float4 av = ap[j];
        a = fmaf(hv.x, av.x, a);
        a = fmaf(hv.y, av.y, a);
        a = fmaf(hv.z, av.z, a);
        a = fmaf(hv.w, av.w, a);
    }
    a += __shfl_xor_sync(0xffffffffu, a, 16);
    a += __shfl_xor_sync(0xffffffffu, a, 8);
    a += __shfl_xor_sync(0xffffffffu, a, 4);
    a += __shfl_xor_sync(0xffffffffu, a, 2);
    a += __shfl_xor_sync(0xffffffffu, a, 1);
    if (lane == 0) out[t] = a + by[0];
}

/* =================== launch =================== */
extern "C" void kernel_launch(void* const* d_in, const int* in_sizes, int n_in,
                              void* d_out, int out_size)
{
    const float* x   = (const float*)d_in[0];
    const float* Wf  = (const float*)d_in[1];
    const float* Uf  = (const float*)d_in[2];
    const float* bf  = (const float*)d_in[3];
    const float* Wi  = (const float*)d_in[4];
    const float* Ui  = (const float*)d_in[5];
    const float* bi  = (const float*)d_in[6];
    const float* Wo  = (const float*)d_in[7];
    const float* Uo  = (const float*)d_in[8];
    const float* bo  = (const float*)d_in[9];
    const float* Wc  = (const float*)d_in[10];
    const float* Uc  = (const float*)d_in[11];
    const float* bc  = (const float*)d_in[12];
    const float* Ahy = (const float*)d_in[13];
    const float* by  = (const float*)d_in[14];
    float* out = (float*)d_out;

    init_kernel<<<1, 512>>>();

    dim3 ggrid((STEPS + GT_TT - 1) / GT_TT, NROWS / GT_ROWS);  /* 32 x 128 */
    gates_kernel<<<ggrid, GT_TPB>>>(x, Wf, Wi, Wo, Wc, bf, bi, bo, bc);

    rec_kernel<<<NCTA, TPB>>>(Uf, Ui, Uo, Uc);

    out_kernel<<<(STEPS + 7) / 8, 256>>>(Ahy, by, out);
}

// round 5
// speedup vs baseline: 7.8255x; 7.8255x over previous
#include <cuda_runtime.h>

#define T_LEN 16384
#define NXW   128
#define NH    512
#define STEPS (T_LEN - NXW)       /* 16256 */
#define NROWS (4 * NH)            /* 2048 gate rows */

#define NCTA  128
#define TPB   128                 /* 4 warps -> 512 warps total = NH */
#define WPC   (TPB / 32)

/* ---- static scratch ---- */
__device__ __align__(16) float  g_XG[(size_t)NROWS * STEPS];     /* [row][t], row=h*4+g */
__device__ __align__(16) float2 g_HP[(size_t)(STEPS + 1) * NH];  /* (h_value, tag_bits) */

/* =================== init =================== */
__global__ void init_kernel() {
    int i = blockIdx.x * blockDim.x + threadIdx.x;
    if (i < NH) g_HP[i] = make_float2(0.0f, __uint_as_float(0u));
}

/* =================== gate precompute =================== */
#define GT_TPB  128
#define GT_TT   512
#define GT_ROWS 16

__global__ void __launch_bounds__(GT_TPB) gates_kernel(
    const float* __restrict__ x,
    const float* __restrict__ Wf, const float* __restrict__ Wi,
    const float* __restrict__ Wo, const float* __restrict__ Wc,
    const float* __restrict__ bf, const float* __restrict__ bi,
    const float* __restrict__ bo, const float* __restrict__ bc)
{
    __shared__ float xs[GT_TT + NXW];
    __shared__ float ws[GT_ROWS * NXW];
    __shared__ float bs[GT_ROWS];

    const int tid = threadIdx.x;
    const int t0  = blockIdx.x * GT_TT;
    const int r0  = blockIdx.y * GT_ROWS;

    for (int i = tid; i < GT_TT + NXW; i += GT_TPB) {
        int xi = t0 + i;
        xs[i] = (xi < T_LEN) ? x[xi] : 0.0f;
    }
    for (int i = tid; i < GT_ROWS * NXW; i += GT_TPB) {
        int lr = i >> 7;
        int k  = i & 127;
        int r  = r0 + lr;
        int g  = r & 3;
        int h  = r >> 2;
        const float* W = (g == 0) ? Wf : (g == 1) ? Wi : (g == 2) ? Wo : Wc;
        ws[i] = W[h * NXW + k];
    }
    if (tid < GT_ROWS) {
        int r = r0 + tid;
        int g = r & 3;
        int h = r >> 2;
        const float* B = (g == 0) ? bf : (g == 1) ? bi : (g == 2) ? bo : bc;
        bs[tid] = B[h];
    }
    __syncthreads();

    float acc0[GT_ROWS], acc1[GT_ROWS], acc2[GT_ROWS], acc3[GT_ROWS];
#pragma unroll
    for (int lr = 0; lr < GT_ROWS; lr++) { acc0[lr] = acc1[lr] = acc2[lr] = acc3[lr] = 0.0f; }

#pragma unroll 4
    for (int k = 0; k < NXW; k++) {
        float x0 = xs[tid + k];
        float x1 = xs[tid + 128 + k];
        float x2 = xs[tid + 256 + k];
        float x3 = xs[tid + 384 + k];
#pragma unroll
        for (int lr = 0; lr < GT_ROWS; lr++) {
            float w = ws[lr * NXW + k];
            acc0[lr] = fmaf(w, x0, acc0[lr]);
            acc1[lr] = fmaf(w, x1, acc1[lr]);
            acc2[lr] = fmaf(w, x2, acc2[lr]);
            acc3[lr] = fmaf(w, x3, acc3[lr]);
        }
    }

#pragma unroll
    for (int lr = 0; lr < GT_ROWS; lr++) {
        size_t base = (size_t)(r0 + lr) * STEPS;
        int t;
        t = t0 + tid;       if (t < STEPS) g_XG[base + t] = acc0[lr] + bs[lr];
        t = t0 + 128 + tid; if (t < STEPS) g_XG[base + t] = acc1[lr] + bs[lr];
        t = t0 + 256 + tid; if (t < STEPS) g_XG[base + t] = acc2[lr] + bs[lr];
        t = t0 + 384 + tid; if (t < STEPS) g_XG[base + t] = acc3[lr] + bs[lr];
    }
}

/* =================== recurrence =================== */
__device__ __forceinline__ float sigmoid_f(float v) {
    float e = __expf(-v);
    return __fdividef(1.0f, 1.0f + e);
}
__device__ __forceinline__ float tanh_f(float v) {
    float e = __expf(2.0f * v);
    return __fdividef(e - 1.0f, e + 1.0f);
}

__device__ __forceinline__ float4 poll_ld(const void* p) {
    float4 v;
    asm volatile("ld.global.cg.v4.f32 {%0,%1,%2,%3}, [%4];"
                 : "=f"(v.x), "=f"(v.y), "=f"(v.z), "=f"(v.w)
                 : "l"(p) : "memory");
    return v;
}

__global__ void __launch_bounds__(TPB, 1) rec_kernel(
    const float* __restrict__ Uf, const float* __restrict__ Ui,
    const float* __restrict__ Uo, const float* __restrict__ Uc)
{
    const int tid   = threadIdx.x;
    const int w     = tid >> 5;
    const int lane  = tid & 31;
    const int h_idx = blockIdx.x * WPC + w;      /* 0..511, one warp per hidden unit */

    /* U weights matched to the coalesced entry order:
       lane L, slot j covers h entries {j*64+2L, j*64+2L+1} */
    const size_t ub = (size_t)h_idx * NH + 2 * lane;
    float2 wf[8], wi[8], wo[8], wc[8];
#pragma unroll
    for (int j = 0; j < 8; j++) {
        wf[j] = *(const float2*)(Uf + ub + j * 64);
        wi[j] = *(const float2*)(Ui + ub + j * 64);
        wo[j] = *(const float2*)(Uo + ub + j * 64);
        wc[j] = *(const float2*)(Uc + ub + j * 64);
    }

    /* gate precompute streams, depth-2 prefetch */
    const float* xf = g_XG + (size_t)(h_idx * 4 + 0) * STEPS;
    const float* xi = g_XG + (size_t)(h_idx * 4 + 1) * STEPS;
    const float* xo = g_XG + (size_t)(h_idx * 4 + 2) * STEPS;
    const float* xc = g_XG + (size_t)(h_idx * 4 + 3) * STEPS;

    float pf0 = __ldcg(xf + 0), pi0 = __ldcg(xi + 0), po0 = __ldcg(xo + 0), pc0 = __ldcg(xc + 0);
    float pf1 = __ldcg(xf + 1), pi1 = __ldcg(xi + 1), po1 = __ldcg(xo + 1), pc1 = __ldcg(xc + 1);

    float c = 0.0f;   /* cell state, replicated across lanes */

#pragma unroll 2
    for (int t = 0; t < STEPS; t++) {
        const int p = t & 1;
        float xgf = p ? pf1 : pf0;
        float xgi = p ? pi1 : pi0;
        float xgo = p ? po1 : po0;
        float xgc = p ? pc1 : pc0;
        if (t + 2 < STEPS) {
            if (p) { pf1 = __ldcg(xf + t + 2); pi1 = __ldcg(xi + t + 2);
                     po1 = __ldcg(xo + t + 2); pc1 = __ldcg(xc + t + 2); }
            else   { pf0 = __ldcg(xf + t + 2); pi0 = __ldcg(xi + t + 2);
                     po0 = __ldcg(xo + t + 2); pc0 = __ldcg(xc + t + 2); }
        }

        /* ---- poll h(t): coalesced — lane L, slot j -> byte j*512 + L*16 ---- */
        const char* rowp = (const char*)(g_HP + (size_t)t * NH) + lane * 16;
        const unsigned tgt = (unsigned)t;
        float4 v0, v1, v2, v3, v4, v5, v6, v7;
        for (;;) {
            v0 = poll_ld(rowp + 0 * 512); v1 = poll_ld(rowp + 1 * 512);
            v2 = poll_ld(rowp + 2 * 512); v3 = poll_ld(rowp + 3 * 512);
            v4 = poll_ld(rowp + 4 * 512); v5 = poll_ld(rowp + 5 * 512);
            v6 = poll_ld(rowp + 6 * 512); v7 = poll_ld(rowp + 7 * 512);
            bool ok = (__float_as_uint(v0.y) == tgt) & (__float_as_uint(v0.w) == tgt)
                    & (__float_as_uint(v1.y) == tgt) & (__float_as_uint(v1.w) == tgt)
                    & (__float_as_uint(v2.y) == tgt) & (__float_as_uint(v2.w) == tgt)
                    & (__float_as_uint(v3.y) == tgt) & (__float_as_uint(v3.w) == tgt)
                    & (__float_as_uint(v4.y) == tgt) & (__float_as_uint(v4.w) == tgt)
                    & (__float_as_uint(v5.y) == tgt) & (__float_as_uint(v5.w) == tgt)
                    & (__float_as_uint(v6.y) == tgt) & (__float_as_uint(v6.w) == tgt)
                    & (__float_as_uint(v7.y) == tgt) & (__float_as_uint(v7.w) == tgt);
            if (__all_sync(0xffffffffu, ok)) break;
            __nanosleep(40);
        }

        /* ---- 4 dots: lane's 16 h values, in coalesced entry order ---- */
        float af = 0.0f, ai = 0.0f, ao = 0.0f, ac = 0.0f;
#define ACC(J, V)                                                     \
        af = fmaf(wf[J].x, V.x, af); af = fmaf(wf[J].y, V.z, af);     \
        ai = fmaf(wi[J].x, V.x, ai); ai = fmaf(wi[J].y, V.z, ai);     \
        ao = fmaf(wo[J].x, V.x, ao); ao = fmaf(wo[J].y, V.z, ao);     \
        ac = fmaf(wc[J].x, V.x, ac); ac = fmaf(wc[J].y, V.z, ac);
        ACC(0, v0) ACC(1, v1) ACC(2, v2) ACC(3, v3)
        ACC(4, v4) ACC(5, v5) ACC(6, v6) ACC(7, v7)
#undef ACC

#pragma unroll
        for (int off = 16; off > 0; off >>= 1) {
            af += __shfl_xor_sync(0xffffffffu, af, off);
            ai += __shfl_xor_sync(0xffffffffu, ai, off);
            ao += __shfl_xor_sync(0xffffffffu, ao, off);
            ac += __shfl_xor_sync(0xffffffffu, ac, off);
        }

        float fg = sigmoid_f(af + xgf);
        float ig = sigmoid_f(ai + xgi);
        float og = sigmoid_f(ao + xgo);
        float gg = tanh_f(ac + xgc);
        c = fmaf(fg, c, ig * gg);
        float hval = og * tanh_f(c);

        if (lane == 0) {
            float2 pr = make_float2(hval, __uint_as_float((unsigned)(t + 1)));
            __stcg(&g_HP[(size_t)(t + 1) * NH + h_idx], pr);
        }
    }
}

/* =================== output GEMV =================== */
__global__ void __launch_bounds__(256) out_kernel(
    const float* __restrict__ Ahy, const float* __restrict__ by,
    float* __restrict__ out)
{
    const int w    = threadIdx.x >> 5;
    const int lane = threadIdx.x & 31;
    const int t    = blockIdx.x * 8 + w;
    if (t >= STEPS) return;

    const char* rowp = (const char*)(g_HP + (size_t)(t + 1) * NH) + lane * 16;
    const size_t ab  = 2 * lane;
    float a = 0.0f;
#pragma unroll
    for (int j = 0; j < 8; j++) {
        float4 v = *(const float4*)(rowp + j * 512);
        float2 av = *(const float2*)(Ahy + ab + j * 64);
        a = fmaf(av.x, v.x, a);
        a = fmaf(av.y, v.z, a);
    }
    a += __shfl_xor_sync(0xffffffffu, a, 16);
    a += __shfl_xor_sync(0xffffffffu, a, 8);
    a += __shfl_xor_sync(0xffffffffu, a, 4);
    a += __shfl_xor_sync(0xffffffffu, a, 2);
    a += __shfl_xor_sync(0xffffffffu, a, 1);
    if (lane == 0) out[t] = a + by[0];
}

/* =================== launch =================== */
extern "C" void kernel_launch(void* const* d_in, const int* in_sizes, int n_in,
                              void* d_out, int out_size)
{
    const float* x   = (const float*)d_in[0];
    const float* Wf  = (const float*)d_in[1];
    const float* Uf  = (const float*)d_in[2];
    const float* bf  = (const float*)d_in[3];
    const float* Wi  = (const float*)d_in[4];
    const float* Ui  = (const float*)d_in[5];
    const float* bi  = (const float*)d_in[6];
    const float* Wo  = (const float*)d_in[7];
    const float* Uo  = (const float*)d_in[8];
    const float* bo  = (const float*)d_in[9];
    const float* Wc  = (const float*)d_in[10];
    const float* Uc  = (const float*)d_in[11];
    const float* bc  = (const float*)d_in[12];
    const float* Ahy = (const float*)d_in[13];
    const float* by  = (const float*)d_in[14];
    float* out = (float*)d_out;

    init_kernel<<<1, 512>>>();

    dim3 ggrid((STEPS + GT_TT - 1) / GT_TT, NROWS / GT_ROWS);
    gates_kernel<<<ggrid, GT_TPB>>>(x, Wf, Wi, Wo, Wc, bf, bi, bo, bc);

    rec_kernel<<<NCTA, TPB>>>(Uf, Ui, Uo, Uc);

    out_kernel<<<(STEPS + 7) / 8, 256>>>(Ahy, by, out);
}